// round 14
// baseline (speedup 1.0000x reference)
#include <cuda_runtime.h>
#include <cstdint>

// Shapes fixed by setup_inputs: x [4,2048,4096] f32, W [4096,4096] int8
// (delivered by harness as int32), wscale [4096] f32, bias [4096] f32.
#define D_IN  4096
#define D_OUT 4096
#define MAX_T 8192

__device__ int8_t g_xq[(size_t)MAX_T * D_IN];
__device__ float  g_xscale[MAX_T];
__device__ int8_t g_wq[(size_t)D_OUT * D_IN];
__device__ int    g_dummy[1];

// ===========================================================================
// Helpers
// ===========================================================================
__device__ __forceinline__ uint32_t smem_u32(const void* p) {
    uint32_t a;
    asm("{ .reg .u64 t; cvta.to.shared.u64 t, %1; cvt.u32.u64 %0, t; }"
        : "=r"(a) : "l"(p));
    return a;
}
#define CP_ASYNC16(dst, src) \
    asm volatile("cp.async.cg.shared.global [%0], [%1], 16;" \
                 :: "r"(dst), "l"(src) : "memory")
#define CP_COMMIT() asm volatile("cp.async.commit_group;" ::: "memory")
#define CP_WAIT(n)  asm volatile("cp.async.wait_group %0;" :: "n"(n) : "memory")
#define CP_WAIT_ALL() asm volatile("cp.async.wait_all;" ::: "memory")

#define LDMATRIX_X4(r0, r1, r2, r3, addr)                                     \
    asm volatile("ldmatrix.sync.aligned.m8n8.x4.shared.b16 {%0,%1,%2,%3}, [%4];" \
                 : "=r"(r0), "=r"(r1), "=r"(r2), "=r"(r3) : "r"(addr))

__device__ __forceinline__ void lds128(int4& v, uint32_t addr) {
    asm volatile("ld.shared.v4.b32 {%0,%1,%2,%3}, [%4];"
                 : "=r"(v.x), "=r"(v.y), "=r"(v.z), "=r"(v.w) : "r"(addr));
}

__device__ __forceinline__ void mma_i8(int* c, const uint32_t* a, const uint32_t* b) {
    asm volatile(
        "mma.sync.aligned.m16n8k32.row.col.s32.s8.s8.s32 "
        "{%0,%1,%2,%3}, {%4,%5,%6,%7}, {%8,%9}, {%0,%1,%2,%3};"
        : "+r"(c[0]), "+r"(c[1]), "+r"(c[2]), "+r"(c[3])
        : "r"(a[0]), "r"(a[1]), "r"(a[2]), "r"(a[3]), "r"(b[0]), "r"(b[1]));
}

// ===========================================================================
// Dummy kernel: keeps the GEMM on ncu's captured launch slot.
// ===========================================================================
__global__ void dummy_kernel() { g_dummy[0] = 1; }

// ===========================================================================
// Fused prep: weight repack (int32->int8) + per-token quantization.
// ===========================================================================
#define PACK_BLOCKS 16384

__global__ __launch_bounds__(256) void prep_kernel(
    const int* __restrict__ w32, const float* __restrict__ x)
{
    if (blockIdx.x < PACK_BLOCKS) {
        const size_t i = (size_t)blockIdx.x * blockDim.x + threadIdx.x;
        const int4 v = reinterpret_cast<const int4*>(w32)[i];
        reinterpret_cast<int*>(g_wq)[i] =
            (v.x & 0xFF) | ((v.y & 0xFF) << 8) | ((v.z & 0xFF) << 16) | ((v.w & 0xFF) << 24);
        return;
    }
    const int t = blockIdx.x - PACK_BLOCKS;
    const float4* __restrict__ xr = reinterpret_cast<const float4*>(x + (size_t)t * D_IN);

    float4 v[4];
    float amax = 0.0f;
#pragma unroll
    for (int i = 0; i < 4; i++) {
        v[i] = xr[threadIdx.x + i * 256];
        amax = fmaxf(amax, fmaxf(fmaxf(fabsf(v[i].x), fabsf(v[i].y)),
                                 fmaxf(fabsf(v[i].z), fabsf(v[i].w))));
    }
    __shared__ float red[8];
#pragma unroll
    for (int o = 16; o > 0; o >>= 1)
        amax = fmaxf(amax, __shfl_xor_sync(0xffffffffu, amax, o));
    if ((threadIdx.x & 31) == 0) red[threadIdx.x >> 5] = amax;
    __syncthreads();
    float m = red[0];
#pragma unroll
    for (int w = 1; w < 8; w++) m = fmaxf(m, red[w]);

    const float scale = fmaxf(m, 1e-8f) / 127.0f;
    if (threadIdx.x == 0) g_xscale[t] = scale;

    int* __restrict__ outw = reinterpret_cast<int*>(g_xq + (size_t)t * D_IN);
#pragma unroll
    for (int i = 0; i < 4; i++) {
        int q0 = (int)fminf(fmaxf(rintf(v[i].x / scale), -128.0f), 127.0f);
        int q1 = (int)fminf(fmaxf(rintf(v[i].y / scale), -128.0f), 127.0f);
        int q2 = (int)fminf(fmaxf(rintf(v[i].z / scale), -128.0f), 127.0f);
        int q3 = (int)fminf(fmaxf(rintf(v[i].w / scale), -128.0f), 127.0f);
        outw[threadIdx.x + i * 256] = (q0 & 0xFF) | ((q1 & 0xFF) << 8) |
                                      ((q2 & 0xFF) << 16) | ((q3 & 0xFF) << 24);
    }
}

// ===========================================================================
// HYBRID int8 GEMM, R14: MERGED-WARP design. Every one of 16 warps drives
// BOTH pipes: a 32x32 mma.sync sub-tile (cols [0,128), 4x4 warp grid) AND
// an 8-row dp4a slice of cols [128,256). Each SMSP then has 4 warps all
// carrying both instruction classes, so dp4a issue fills tensor-pipe
// latency and vice versa — removes the specialized-warp straggler problem
// (R11-R13: issue<=48%, tensor<=76%, both pipes starved).
// Tile 128x256, BK=128, 3-stage cp.async, one barrier per iter, 512 thr.
// ===========================================================================
#define BM 128
#define BN_T 128
#define BN_D 128
#define BN (BN_T + BN_D)         // 256
#define BK 128
#define STAGES 3
#define NKB (D_IN / BK)          // 32
#define ROW_B 144                // 128B data + 16B pad
#define A_TILE (BM * ROW_B)      // 18432
#define BT_TILE (BN_T * ROW_B)   // 18432
#define STAGE_T (A_TILE + BT_TILE)           // 36864
#define OFF_B2 (STAGES * STAGE_T)            // 110592
#define B2_TILE (8 * BN_D * 16)              // 16384 ([kw8][col] int4)
#define SMEM_TOTAL (OFF_B2 + STAGES * B2_TILE)   // 159744

__global__ __launch_bounds__(512, 1) void gemm_hybrid_kernel(
    const float* __restrict__ wscale,
    const float* __restrict__ bias,
    float* __restrict__ out)
{
    extern __shared__ char smem[];
    const uint32_t sbase = smem_u32(smem);

    const int tid  = threadIdx.x;
    const int lane = tid & 31;
    const int wid  = tid >> 5;

    const int m0 = blockIdx.y * BM;
    const int n0 = blockIdx.x * BN;

    // ---- tensor sub-tile: 4(M) x 4(N) warp grid over 128x128 ----
    const int wm = wid & 3;          // rows wm*32 .. +32
    const int wn = wid >> 2;         // cols wn*32 .. +32
    const int g  = lane >> 2;
    const int tq = lane & 3;

    int acc_t[2][4][4];              // [mt][nt][reg]
#pragma unroll
    for (int mt = 0; mt < 2; mt++)
#pragma unroll
        for (int nt = 0; nt < 4; nt++)
#pragma unroll
            for (int r = 0; r < 4; r++) acc_t[mt][nt][r] = 0;

    // ---- dp4a slice: warp wid owns rows wid*8..+8 of cols [128,256);
    //      lane handles cols lane + j*32 (j=0..3) -> acc_d[8 rows][4 cols]
    int acc_d[8][4];
#pragma unroll
    for (int i = 0; i < 8; i++)
#pragma unroll
        for (int j = 0; j < 4; j++) acc_d[i][j] = 0;

    // ---- stage loader: A 1024 + B_T 1024 + B2 1024 chunks, 512 threads ----
    auto load_stage = [&](int s, int kb) {
        const uint32_t sa = sbase + s * STAGE_T;
        const uint32_t sb = sa + A_TILE;
        const uint32_t b2 = sbase + OFF_B2 + s * B2_TILE;
        const size_t kcol = (size_t)kb * BK;
#pragma unroll
        for (int c = 0; c < 2; c++) {
            const int idx = tid + c * 512;               // A
            const int row = idx >> 3, kw = idx & 7;
            CP_ASYNC16(sa + row * ROW_B + kw * 16,
                       g_xq + (size_t)(m0 + row) * D_IN + kcol + kw * 16);
        }
#pragma unroll
        for (int c = 0; c < 2; c++) {
            const int idx = tid + c * 512;               // B tensor
            const int row = idx >> 3, kw = idx & 7;
            CP_ASYNC16(sb + row * ROW_B + kw * 16,
                       g_wq + (size_t)(n0 + row) * D_IN + kcol + kw * 16);
        }
#pragma unroll
        for (int c = 0; c < 2; c++) {
            const int idx = tid + c * 512;               // B dp4a
            const int col = idx >> 3, kw = idx & 7;
            CP_ASYNC16(b2 + (kw * BN_D + col) * 16,
                       g_wq + (size_t)(n0 + BN_T + col) * D_IN + kcol + kw * 16);
        }
    };

#pragma unroll
    for (int s = 0; s < STAGES - 1; s++) {
        load_stage(s, s);
        CP_COMMIT();
    }

    // ---- ldmatrix addresses ----
    const int a_row = wm * 32 + (lane & 7) + ((lane >> 3) & 1) * 8;
    const int a_b16 = (lane >> 4) * 16;
    uint32_t a_lo[2];
#pragma unroll
    for (int mt = 0; mt < 2; mt++)
        a_lo[mt] = (uint32_t)((a_row + mt * 16) * ROW_B + a_b16);

    const int b_row = wn * 32 + (lane & 7) + ((lane >> 4) & 1) * 8;
    const int b_b16 = ((lane >> 3) & 1) * 16;
    uint32_t b_lo[2];
#pragma unroll
    for (int t = 0; t < 2; t++)
        b_lo[t] = (uint32_t)(A_TILE + (b_row + t * 16) * ROW_B + b_b16);

    // ---- main loop ----
#pragma unroll 1
    for (int kb = 0; kb < NKB; kb++) {
        CP_WAIT(STAGES - 2);
        __syncthreads();

        const int pf = kb + STAGES - 1;
        if (pf < NKB) load_stage(pf % STAGES, pf);
        CP_COMMIT();

        const int s = kb % STAGES;
        const uint32_t st = sbase + s * STAGE_T;
        const uint32_t a_t = st;                          // A tile (dp4a reads too)
        const uint32_t b2 = sbase + OFF_B2 + s * B2_TILE;

        // interleave tensor ks-blocks with dp4a kw-blocks so both pipe
        // classes are live in every scheduling window
#pragma unroll
        for (int ks = 0; ks < 4; ks++) {
            // tensor: one K=32 step (8 MMAs)
            {
                const uint32_t ko = ks * 32;
                uint32_t af[2][4], bf[4][2];
#pragma unroll
                for (int mt = 0; mt < 2; mt++)
                    LDMATRIX_X4(af[mt][0], af[mt][1], af[mt][2], af[mt][3],
                                st + a_lo[mt] + ko);
                LDMATRIX_X4(bf[0][0], bf[0][1], bf[1][0], bf[1][1], st + b_lo[0] + ko);
                LDMATRIX_X4(bf[2][0], bf[2][1], bf[3][0], bf[3][1], st + b_lo[1] + ko);
#pragma unroll
                for (int mt = 0; mt < 2; mt++)
#pragma unroll
                    for (int nt = 0; nt < 4; nt++)
                        mma_i8(acc_t[mt][nt], af[mt], bf[nt]);
            }
            // dp4a: two 16B K-chunks (kw = 2ks, 2ks+1)
#pragma unroll
            for (int h = 0; h < 2; h++) {
                const int kw = ks * 2 + h;
                int4 b4[4];
#pragma unroll
                for (int j = 0; j < 4; j++)
                    lds128(b4[j], b2 + (kw * BN_D + j * 32 + lane) * 16);
#pragma unroll
                for (int i = 0; i < 8; i++) {
                    int4 a4;
                    lds128(a4, a_t + (wid * 8 + i) * ROW_B + kw * 16);   // broadcast
#pragma unroll
                    for (int j = 0; j < 4; j++) {
                        acc_d[i][j] = __dp4a(a4.x, b4[j].x, acc_d[i][j]);
                        acc_d[i][j] = __dp4a(a4.y, b4[j].y, acc_d[i][j]);
                        acc_d[i][j] = __dp4a(a4.z, b4[j].z, acc_d[i][j]);
                        acc_d[i][j] = __dp4a(a4.w, b4[j].w, acc_d[i][j]);
                    }
                }
            }
        }
    }

    // ---- epilogue ----
    CP_WAIT_ALL();
    __syncthreads();
    float* ws_s = reinterpret_cast<float*>(smem);
    float* bs_s = ws_s + BN;
    if (tid < BN) {
        ws_s[tid] = wscale[n0 + tid];
        bs_s[tid] = bias[n0 + tid];
    }
    __syncthreads();

    // tensor epilogue (cols [0,128))
#pragma unroll
    for (int mt = 0; mt < 2; mt++) {
        const int row0 = m0 + wm * 32 + mt * 16 + g;
        const float xs0 = g_xscale[row0];
        const float xs1 = g_xscale[row0 + 8];
        float* __restrict__ o0 = out + (size_t)row0 * D_OUT;
        float* __restrict__ o1 = out + (size_t)(row0 + 8) * D_OUT;
#pragma unroll
        for (int nt = 0; nt < 4; nt++) {
            const int nl = wn * 32 + nt * 8 + tq * 2;
            const float w0 = ws_s[nl], w1 = ws_s[nl + 1];
            const float b0 = bs_s[nl], b1 = bs_s[nl + 1];
            float2 v0, v1;
            v0.x = (float)acc_t[mt][nt][0] * xs0 * w0 + b0;
            v0.y = (float)acc_t[mt][nt][1] * xs0 * w1 + b1;
            v1.x = (float)acc_t[mt][nt][2] * xs1 * w0 + b0;
            v1.y = (float)acc_t[mt][nt][3] * xs1 * w1 + b1;
            *reinterpret_cast<float2*>(o0 + n0 + nl) = v0;
            *reinterpret_cast<float2*>(o1 + n0 + nl) = v1;
        }
    }

    // dp4a epilogue (cols [128,256)): rows wid*8+i, cols lane + j*32
#pragma unroll
    for (int i = 0; i < 8; i++) {
        const int m = m0 + wid * 8 + i;
        const float xs = g_xscale[m];
        float* __restrict__ orow = out + (size_t)m * D_OUT;
#pragma unroll
        for (int j = 0; j < 4; j++) {
            const int nl = BN_T + j * 32 + lane;
            orow[n0 + nl] = (float)acc_d[i][j] * xs * ws_s[nl] + bs_s[nl];
        }
    }
}

// ===========================================================================
extern "C" void kernel_launch(void* const* d_in, const int* in_sizes, int n_in,
                              void* d_out, int out_size)
{
    const float* x      = (const float*)d_in[0];
    const int*   w32    = (const int*)d_in[1];
    const float* wscale = (const float*)d_in[2];
    const float* bias   = (const float*)d_in[3];
    float*       out    = (float*)d_out;

    const int T = in_sizes[0] / D_IN;   // 8192

    prep_kernel<<<PACK_BLOCKS + T, 256>>>(w32, x);
    dummy_kernel<<<1, 32>>>();
    dummy_kernel<<<1, 32>>>();

    static bool attr_set = false;
    if (!attr_set) {
        cudaFuncSetAttribute(gemm_hybrid_kernel,
                             cudaFuncAttributeMaxDynamicSharedMemorySize, SMEM_TOTAL);
        attr_set = true;
    }
    dim3 grid(D_OUT / BN, T / BM);      // (16, 64)
    gemm_hybrid_kernel<<<grid, 512, SMEM_TOTAL>>>(wscale, bias, out);
}

// round 16
// speedup vs baseline: 1.3788x; 1.3788x over previous
#include <cuda_runtime.h>
#include <cstdint>

// Shapes fixed by setup_inputs: x [4,2048,4096] f32, W [4096,4096] int8
// (delivered by harness as int32), wscale [4096] f32, bias [4096] f32.
#define D_IN  4096
#define D_OUT 4096
#define MAX_T 8192

__device__ int8_t g_xq[(size_t)MAX_T * D_IN];
__device__ float  g_xscale[MAX_T];
__device__ int8_t g_wq[(size_t)D_OUT * D_IN];

// ===========================================================================
// Helpers
// ===========================================================================
__device__ __forceinline__ uint32_t smem_u32(const void* p) {
    uint32_t a;
    asm("{ .reg .u64 t; cvta.to.shared.u64 t, %1; cvt.u32.u64 %0, t; }"
        : "=r"(a) : "l"(p));
    return a;
}
#define CP_ASYNC16(dst, src) \
    asm volatile("cp.async.cg.shared.global [%0], [%1], 16;" \
                 :: "r"(dst), "l"(src) : "memory")
#define CP_COMMIT() asm volatile("cp.async.commit_group;" ::: "memory")
#define CP_WAIT(n)  asm volatile("cp.async.wait_group %0;" :: "n"(n) : "memory")
#define CP_WAIT_ALL() asm volatile("cp.async.wait_all;" ::: "memory")

#define LDMATRIX_X4(r0, r1, r2, r3, addr)                                     \
    asm volatile("ldmatrix.sync.aligned.m8n8.x4.shared.b16 {%0,%1,%2,%3}, [%4];" \
                 : "=r"(r0), "=r"(r1), "=r"(r2), "=r"(r3) : "r"(addr))
#define LDMATRIX_X2(r0, r1, addr)                                             \
    asm volatile("ldmatrix.sync.aligned.m8n8.x2.shared.b16 {%0,%1}, [%2];"    \
                 : "=r"(r0), "=r"(r1) : "r"(addr))

__device__ __forceinline__ void lds128(int4& v, uint32_t addr) {
    asm volatile("ld.shared.v4.b32 {%0,%1,%2,%3}, [%4];"
                 : "=r"(v.x), "=r"(v.y), "=r"(v.z), "=r"(v.w) : "r"(addr));
}

__device__ __forceinline__ void mma_i8(int* c, const uint32_t* a, const uint32_t* b) {
    asm volatile(
        "mma.sync.aligned.m16n8k32.row.col.s32.s8.s8.s32 "
        "{%0,%1,%2,%3}, {%4,%5,%6,%7}, {%8,%9}, {%0,%1,%2,%3};"
        : "+r"(c[0]), "+r"(c[1]), "+r"(c[2]), "+r"(c[3])
        : "r"(a[0]), "r"(a[1]), "r"(a[2]), "r"(a[3]), "r"(b[0]), "r"(b[1]));
}

// ===========================================================================
// Fused prep: weight repack (int32->int8) + per-token quantization.
// ===========================================================================
#define PACK_BLOCKS 16384

__global__ __launch_bounds__(256) void prep_kernel(
    const int* __restrict__ w32, const float* __restrict__ x)
{
    if (blockIdx.x < PACK_BLOCKS) {
        const size_t i = (size_t)blockIdx.x * blockDim.x + threadIdx.x;
        const int4 v = reinterpret_cast<const int4*>(w32)[i];
        reinterpret_cast<int*>(g_wq)[i] =
            (v.x & 0xFF) | ((v.y & 0xFF) << 8) | ((v.z & 0xFF) << 16) | ((v.w & 0xFF) << 24);
        return;
    }
    const int t = blockIdx.x - PACK_BLOCKS;
    const float4* __restrict__ xr = reinterpret_cast<const float4*>(x + (size_t)t * D_IN);

    float4 v[4];
    float amax = 0.0f;
#pragma unroll
    for (int i = 0; i < 4; i++) {
        v[i] = xr[threadIdx.x + i * 256];
        amax = fmaxf(amax, fmaxf(fmaxf(fabsf(v[i].x), fabsf(v[i].y)),
                                 fmaxf(fabsf(v[i].z), fabsf(v[i].w))));
    }
    __shared__ float red[8];
#pragma unroll
    for (int o = 16; o > 0; o >>= 1)
        amax = fmaxf(amax, __shfl_xor_sync(0xffffffffu, amax, o));
    if ((threadIdx.x & 31) == 0) red[threadIdx.x >> 5] = amax;
    __syncthreads();
    float m = red[0];
#pragma unroll
    for (int w = 1; w < 8; w++) m = fmaxf(m, red[w]);

    const float scale = fmaxf(m, 1e-8f) / 127.0f;
    if (threadIdx.x == 0) g_xscale[t] = scale;

    int* __restrict__ outw = reinterpret_cast<int*>(g_xq + (size_t)t * D_IN);
#pragma unroll
    for (int i = 0; i < 4; i++) {
        int q0 = (int)fminf(fmaxf(rintf(v[i].x / scale), -128.0f), 127.0f);
        int q1 = (int)fminf(fmaxf(rintf(v[i].y / scale), -128.0f), 127.0f);
        int q2 = (int)fminf(fmaxf(rintf(v[i].z / scale), -128.0f), 127.0f);
        int q3 = (int)fminf(fmaxf(rintf(v[i].w / scale), -128.0f), 127.0f);
        outw[threadIdx.x + i * 256] = (q0 & 0xFF) | ((q1 & 0xFF) << 8) |
                                      ((q2 & 0xFF) << 16) | ((q3 & 0xFF) << 24);
    }
}

// ===========================================================================
// HYBRID int8 GEMM — R10 best config (tensor 144 cols / dp4a 112 cols,
// BK=128, 3-stage cp.async, shared A tile, one barrier per iter, 512 thr,
// specialized warps) + dp4a i-loop software pipelining (the one R12 change
// that was never tested at the balanced split).
// ===========================================================================
#define BM 128
#define BN_T 144
#define BN_D 112
#define BN (BN_T + BN_D)         // 256
#define BK 128
#define STAGES 3
#define NKB (D_IN / BK)          // 32
#define ROW_B 144                // 128B data + 16B pad
#define A_TILE (BM * ROW_B)      // 18432
#define BT_TILE (BN_T * ROW_B)   // 20736
#define STAGE_T (A_TILE + BT_TILE)           // 39168
#define OFF_B2 (STAGES * STAGE_T)            // 117504
#define B2_TILE (8 * BN_D * 16)              // 14336 ([kw8][col] int4)
#define SMEM_TOTAL (OFF_B2 + STAGES * B2_TILE)   // 160512

__global__ __launch_bounds__(512, 1) void gemm_hybrid_kernel(
    const float* __restrict__ wscale,
    const float* __restrict__ bias,
    float* __restrict__ out)
{
    extern __shared__ char smem[];
    const uint32_t sbase = smem_u32(smem);

    const int tid  = threadIdx.x;
    const int lane = tid & 31;
    const int wid  = tid >> 5;

    const int m0 = blockIdx.y * BM;
    const int n0 = blockIdx.x * BN;

    if (wid < 8) {
        // ---- TENSOR PATH (warps 0-7): cols [n0, n0+144), warp tile 32x72 ----
        const int g  = lane >> 2;
        const int tq = lane & 3;
        const int wm = wid & 3;
        const int wn = wid >> 2;

        int acc[2][9][4];
#pragma unroll
        for (int mt = 0; mt < 2; mt++)
#pragma unroll
            for (int nt = 0; nt < 9; nt++)
#pragma unroll
                for (int r = 0; r < 4; r++) acc[mt][nt][r] = 0;

        // loader: A 1024 + B 1152 = 2176 16B-chunks per stage, 256 threads
        auto load_stage = [&](int s, int kb) {
            const uint32_t sa = sbase + s * STAGE_T;
            const uint32_t sb = sa + A_TILE;
            const size_t kcol = (size_t)kb * BK;
#pragma unroll
            for (int c = 0; c < 9; c++) {
                const int idx = tid + c * 256;
                if (idx < 1024) {                // A: 128 rows x 8 chunks
                    const int row = idx >> 3, kw = idx & 7;
                    CP_ASYNC16(sa + row * ROW_B + kw * 16,
                               g_xq + (size_t)(m0 + row) * D_IN + kcol + kw * 16);
                } else if (idx < 2176) {         // B: 144 rows x 8 chunks
                    const int i2 = idx - 1024;
                    const int row = i2 >> 3, kw = i2 & 7;
                    CP_ASYNC16(sb + row * ROW_B + kw * 16,
                               g_wq + (size_t)(n0 + row) * D_IN + kcol + kw * 16);
                }
            }
        };

#pragma unroll
        for (int s = 0; s < STAGES - 1; s++) {
            load_stage(s, s);
            CP_COMMIT();
        }

        const int a_row = wm * 32 + (lane & 7) + ((lane >> 3) & 1) * 8;
        const int a_b16 = (lane >> 4) * 16;
        uint32_t a_lo[2];
#pragma unroll
        for (int mt = 0; mt < 2; mt++)
            a_lo[mt] = (uint32_t)((a_row + mt * 16) * ROW_B + a_b16);

        const int b_row = wn * 72 + (lane & 7) + ((lane >> 4) & 1) * 8;
        const int b_b16 = ((lane >> 3) & 1) * 16;
        uint32_t b_lo[4];
#pragma unroll
        for (int t = 0; t < 4; t++)
            b_lo[t] = (uint32_t)(A_TILE + (b_row + t * 16) * ROW_B + b_b16);

        const int b2_row = wn * 72 + 64 + (lane & 7);
        const uint32_t b_lo2 = (uint32_t)(A_TILE + b2_row * ROW_B + b_b16);

#pragma unroll 1
        for (int kb = 0; kb < NKB; kb++) {
            CP_WAIT(STAGES - 2);
            __syncthreads();

            const int pf = kb + STAGES - 1;
            if (pf < NKB) load_stage(pf % STAGES, pf);
            CP_COMMIT();

            const uint32_t st = sbase + (kb % STAGES) * STAGE_T;
#pragma unroll
            for (int ks = 0; ks < 4; ks++) {
                const uint32_t ko = ks * 32;
                uint32_t af[2][4], bf[9][2];
#pragma unroll
                for (int mt = 0; mt < 2; mt++)
                    LDMATRIX_X4(af[mt][0], af[mt][1], af[mt][2], af[mt][3],
                                st + a_lo[mt] + ko);
#pragma unroll
                for (int t = 0; t < 4; t++)
                    LDMATRIX_X4(bf[2 * t][0], bf[2 * t][1], bf[2 * t + 1][0],
                                bf[2 * t + 1][1], st + b_lo[t] + ko);
                LDMATRIX_X2(bf[8][0], bf[8][1], st + b_lo2 + ko);
#pragma unroll
                for (int mt = 0; mt < 2; mt++)
#pragma unroll
                    for (int nt = 0; nt < 9; nt++)
                        mma_i8(acc[mt][nt], af[mt], bf[nt]);
            }
        }

        CP_WAIT_ALL();
        __syncthreads();
        float* ws_s = reinterpret_cast<float*>(smem);
        float* bs_s = ws_s + BN;
        if (tid < BN) {
            ws_s[tid] = wscale[n0 + tid];
            bs_s[tid] = bias[n0 + tid];
        }
        __syncthreads();

#pragma unroll
        for (int mt = 0; mt < 2; mt++) {
            const int row0 = m0 + wm * 32 + mt * 16 + g;
            const float xs0 = g_xscale[row0];
            const float xs1 = g_xscale[row0 + 8];
            float* __restrict__ o0 = out + (size_t)row0 * D_OUT;
            float* __restrict__ o1 = out + (size_t)(row0 + 8) * D_OUT;
#pragma unroll
            for (int nt = 0; nt < 9; nt++) {
                const int nl = wn * 72 + nt * 8 + tq * 2;
                const float w0 = ws_s[nl], w1 = ws_s[nl + 1];
                const float b0 = bs_s[nl], b1 = bs_s[nl + 1];
                float2 v0, v1;
                v0.x = (float)acc[mt][nt][0] * xs0 * w0 + b0;
                v0.y = (float)acc[mt][nt][1] * xs0 * w1 + b1;
                v1.x = (float)acc[mt][nt][2] * xs1 * w0 + b0;
                v1.y = (float)acc[mt][nt][3] * xs1 * w1 + b1;
                *reinterpret_cast<float2*>(o0 + n0 + nl) = v0;
                *reinterpret_cast<float2*>(o1 + n0 + nl) = v1;
            }
        }
    } else {
        // ---- DP4A PATH (warps 8-15): cols [n0+144, n0+256), shared A ----
        const int t2 = tid - 256;
        const int tx = t2 & 15;
        const int ty = t2 >> 4;

        int acc[8][7];
#pragma unroll
        for (int i = 0; i < 8; i++)
#pragma unroll
            for (int j = 0; j < 7; j++) acc[i][j] = 0;

        auto load_stage_d = [&](int s, int kb) {
            const uint32_t b2 = sbase + OFF_B2 + s * B2_TILE;
            const size_t kcol = (size_t)kb * BK;
#pragma unroll
            for (int c = 0; c < 4; c++) {
                const int idx = t2 + c * 256;
                if (idx < 896) {
                    const int col = idx >> 3, kw = idx & 7;
                    CP_ASYNC16(b2 + (kw * BN_D + col) * 16,
                               g_wq + (size_t)(n0 + BN_T + col) * D_IN + kcol + kw * 16);
                }
            }
        };

#pragma unroll
        for (int s = 0; s < STAGES - 1; s++) {
            load_stage_d(s, s);
            CP_COMMIT();
        }

#pragma unroll 1
        for (int kb = 0; kb < NKB; kb++) {
            CP_WAIT(STAGES - 2);
            __syncthreads();

            const int pf = kb + STAGES - 1;
            if (pf < NKB) load_stage_d(pf % STAGES, pf);
            CP_COMMIT();

            const int s = kb % STAGES;
            const uint32_t a_t = sbase + s * STAGE_T;            // shared A
            const uint32_t b2 = sbase + OFF_B2 + s * B2_TILE;

#pragma unroll
            for (int kw = 0; kw < 8; kw++) {
                int4 b[7];
#pragma unroll
                for (int j = 0; j < 7; j++)
                    lds128(b[j], b2 + (kw * BN_D + j * 16 + tx) * 16);

                // software-pipelined i-loop: a[i+1] LDS overlaps dp4a of a[i]
                int4 a_cur, a_nxt;
                lds128(a_cur, a_t + (ty * 8 + 0) * ROW_B + kw * 16);
#pragma unroll
                for (int i = 0; i < 8; i++) {
                    if (i < 7)
                        lds128(a_nxt, a_t + (ty * 8 + i + 1) * ROW_B + kw * 16);
#pragma unroll
                    for (int j = 0; j < 7; j++) {
                        acc[i][j] = __dp4a(a_cur.x, b[j].x, acc[i][j]);
                        acc[i][j] = __dp4a(a_cur.y, b[j].y, acc[i][j]);
                        acc[i][j] = __dp4a(a_cur.z, b[j].z, acc[i][j]);
                        acc[i][j] = __dp4a(a_cur.w, b[j].w, acc[i][j]);
                    }
                    a_cur = a_nxt;
                }
            }
        }

        CP_WAIT_ALL();
        __syncthreads();
        __syncthreads();   // (ws/bs staged by tensor-path threads)

        const float* ws_s = reinterpret_cast<const float*>(smem);
        const float* bs_s = ws_s + BN;
#pragma unroll
        for (int i = 0; i < 8; i++) {
            const int m = m0 + ty * 8 + i;
            const float xs = g_xscale[m];
            float* __restrict__ orow = out + (size_t)m * D_OUT;
#pragma unroll
            for (int j = 0; j < 7; j++) {
                const int nl = BN_T + j * 16 + tx;
                orow[n0 + nl] = (float)acc[i][j] * xs * ws_s[nl] + bs_s[nl];
            }
        }
    }
}

// ===========================================================================
extern "C" void kernel_launch(void* const* d_in, const int* in_sizes, int n_in,
                              void* d_out, int out_size)
{
    const float* x      = (const float*)d_in[0];
    const int*   w32    = (const int*)d_in[1];
    const float* wscale = (const float*)d_in[2];
    const float* bias   = (const float*)d_in[3];
    float*       out    = (float*)d_out;

    const int T = in_sizes[0] / D_IN;   // 8192

    prep_kernel<<<PACK_BLOCKS + T, 256>>>(w32, x);

    static bool attr_set = false;
    if (!attr_set) {
        cudaFuncSetAttribute(gemm_hybrid_kernel,
                             cudaFuncAttributeMaxDynamicSharedMemorySize, SMEM_TOTAL);
        attr_set = true;
    }
    dim3 grid(D_OUT / BN, T / BM);      // (16, 64)
    gemm_hybrid_kernel<<<grid, 512, SMEM_TOTAL>>>(wscale, bias, out);
}